// round 3
// baseline (speedup 1.0000x reference)
#include <cuda_runtime.h>
#include <cuda_bf16.h>

#define BATCH 64
#define NN 1024
#define IN_DIM 256
#define HID 128
#define NEG_SLOPE 0.2f
#define MASK_VAL (-9.0e15f)

// scratch (allocation-free rule: __device__ globals)
__device__ float g_w1[IN_DIM];
__device__ float g_w2[IN_DIM];
__device__ float g_s1[BATCH * NN];
__device__ float g_s2[BATCH * NN];

// ---------------------------------------------------------------------------
// Kernel A: fold attention vector through W:  w1 = W @ a[:HID], w2 = W @ a[HID:]
// W is (IN_DIM, HID) row-major. One block, 256 threads (one per d).
// ---------------------------------------------------------------------------
__global__ void fold_a_kernel(const float* __restrict__ W,
                              const float* __restrict__ a) {
    __shared__ float sa[2 * HID];
    int t = threadIdx.x;               // 0..255
    sa[t] = a[t];                      // 2*HID == 256
    __syncthreads();

    float acc1 = 0.f, acc2 = 0.f;
    const float* wr = W + t * HID;
#pragma unroll 8
    for (int h = 0; h < HID; ++h) {
        float w = wr[h];
        acc1 = fmaf(w, sa[h], acc1);
        acc2 = fmaf(w, sa[HID + h], acc2);
    }
    g_w1[t] = acc1;
    g_w2[t] = acc2;
}

// ---------------------------------------------------------------------------
// Kernel B: s1[r] = context[r,:] . w1 ; s2[r] = context[r,:] . w2
// One warp per row, 8 rows per 256-thread block. float4 coalesced loads.
// ---------------------------------------------------------------------------
__global__ void proj_kernel(const float* __restrict__ ctx) {
    __shared__ float sw1[IN_DIM];
    __shared__ float sw2[IN_DIM];
    int t = threadIdx.x;               // 256 threads
    sw1[t] = g_w1[t];
    sw2[t] = g_w2[t];
    __syncthreads();

    int warp = t >> 5;
    int lane = t & 31;
    long long row = (long long)blockIdx.x * 8 + warp;
    const float4* p = (const float4*)(ctx + row * IN_DIM);

    float acc1 = 0.f, acc2 = 0.f;
#pragma unroll
    for (int k = 0; k < 2; ++k) {
        int idx = k * 32 + lane;       // float4 index within the row (64 total)
        float4 v = p[idx];
        int d = idx * 4;
        acc1 = fmaf(v.x, sw1[d + 0], acc1);
        acc1 = fmaf(v.y, sw1[d + 1], acc1);
        acc1 = fmaf(v.z, sw1[d + 2], acc1);
        acc1 = fmaf(v.w, sw1[d + 3], acc1);
        acc2 = fmaf(v.x, sw2[d + 0], acc2);
        acc2 = fmaf(v.y, sw2[d + 1], acc2);
        acc2 = fmaf(v.z, sw2[d + 2], acc2);
        acc2 = fmaf(v.w, sw2[d + 3], acc2);
    }
#pragma unroll
    for (int o = 16; o; o >>= 1) {
        acc1 += __shfl_down_sync(0xffffffffu, acc1, o);
        acc2 += __shfl_down_sync(0xffffffffu, acc2, o);
    }
    if (lane == 0) {
        g_s1[row] = acc1;
        g_s2[row] = acc2;
    }
}

// ---------------------------------------------------------------------------
// Kernel C: per row (b,i): e[j] = leaky_relu(s1[b,i]+s2[b,j]); mask by adj;
// softmax over j; softplus. One block per row; 256 threads x 4 j's (int4/float4).
// adj read once, logits held in registers -> single pass over adj.
// ---------------------------------------------------------------------------
__global__ void __launch_bounds__(256) attn_kernel(const int* __restrict__ adj,
                                                   float* __restrict__ out) {
    const int row = blockIdx.x;        // b*NN + i
    const int b = row >> 10;

    __shared__ float s2s[NN];
    __shared__ float red_max[8];
    __shared__ float red_sum[8];

    const int t = threadIdx.x;         // 0..255
    const int warp = t >> 5;
    const int lane = t & 31;

#pragma unroll
    for (int k = 0; k < 4; ++k)
        s2s[t + k * 256] = g_s2[b * NN + t + k * 256];
    const float s1v = g_s1[row];
    __syncthreads();

    const int4 a4 = ((const int4*)(adj + (long long)row * NN))[t];
    const int j0 = t * 4;

    float ev[4];
    {
        float e;
        e = s1v + s2s[j0 + 0]; e = (e >= 0.f) ? e : NEG_SLOPE * e; ev[0] = (a4.x > 0) ? e : MASK_VAL;
        e = s1v + s2s[j0 + 1]; e = (e >= 0.f) ? e : NEG_SLOPE * e; ev[1] = (a4.y > 0) ? e : MASK_VAL;
        e = s1v + s2s[j0 + 2]; e = (e >= 0.f) ? e : NEG_SLOPE * e; ev[2] = (a4.z > 0) ? e : MASK_VAL;
        e = s1v + s2s[j0 + 3]; e = (e >= 0.f) ? e : NEG_SLOPE * e; ev[3] = (a4.w > 0) ? e : MASK_VAL;
    }

    // block max
    float m = fmaxf(fmaxf(ev[0], ev[1]), fmaxf(ev[2], ev[3]));
#pragma unroll
    for (int o = 16; o; o >>= 1)
        m = fmaxf(m, __shfl_xor_sync(0xffffffffu, m, o));
    if (lane == 0) red_max[warp] = m;
    __syncthreads();
    m = red_max[0];
#pragma unroll
    for (int w = 1; w < 8; ++w) m = fmaxf(m, red_max[w]);

    // block sum of exp
    float p[4];
    float s = 0.f;
#pragma unroll
    for (int k = 0; k < 4; ++k) {
        p[k] = __expf(ev[k] - m);      // masked -> exp(-huge) == 0
        s += p[k];
    }
#pragma unroll
    for (int o = 16; o; o >>= 1)
        s += __shfl_xor_sync(0xffffffffu, s, o);
    if (lane == 0) red_sum[warp] = s;
    __syncthreads();
    s = red_sum[0];
#pragma unroll
    for (int w = 1; w < 8; ++w) s += red_sum[w];
    const float inv = __frcp_rn(s);

    // softplus(softmax) epilogue, float4 store
    float4 o4;
    o4.x = __logf(1.f + __expf(p[0] * inv));
    o4.y = __logf(1.f + __expf(p[1] * inv));
    o4.z = __logf(1.f + __expf(p[2] * inv));
    o4.w = __logf(1.f + __expf(p[3] * inv));
    ((float4*)(out + (long long)row * NN))[t] = o4;
}

extern "C" void kernel_launch(void* const* d_in, const int* in_sizes, int n_in,
                              void* d_out, int out_size) {
    const float* ctx = (const float*)d_in[0];   // (64,1024,256)
    const float* W   = (const float*)d_in[1];   // (256,128)
    const float* a   = (const float*)d_in[2];   // (256,1)
    const int*   adj = (const int*)d_in[3];     // (64,1024,1024)
    float* out = (float*)d_out;

    fold_a_kernel<<<1, 256>>>(W, a);
    proj_kernel<<<(BATCH * NN) / 8, 256>>>(ctx);
    attn_kernel<<<BATCH * NN, 256>>>(adj, out);
}

// round 4
// speedup vs baseline: 1.6198x; 1.6198x over previous
#include <cuda_runtime.h>
#include <cuda_bf16.h>

#define BATCH 64
#define NN 1024
#define IN_DIM 256
#define HID 128
#define NEG_SLOPE 0.2f
#define MASK_VAL (-9.0e15f)
#define LN2 0.69314718056f

// scratch (allocation-free rule: __device__ globals)
__device__ float g_w1[IN_DIM];
__device__ float g_w2[IN_DIM];
__device__ float g_s1[BATCH * NN];
__device__ float g_s2[BATCH * NN];

// ---------------------------------------------------------------------------
// Kernel A: fold attention vector through W: w1 = W @ a[:HID], w2 = W @ a[HID:]
// Parallel: one warp per output d. 32 blocks x 8 warps = 256 outputs.
// ---------------------------------------------------------------------------
__global__ void fold_a_kernel(const float* __restrict__ W,
                              const float* __restrict__ a) {
    __shared__ float sa[2 * HID];
    const int t = threadIdx.x;         // 0..255
    sa[t] = a[t];
    __syncthreads();

    const int warp = t >> 5;
    const int lane = t & 31;
    const int d = blockIdx.x * 8 + warp;      // 0..255

    // W row d: 128 floats = 32 float4, one per lane
    const float4 wv = ((const float4*)(W + d * HID))[lane];
    const int h = lane * 4;
    float acc1 = wv.x * sa[h + 0] + wv.y * sa[h + 1]
               + wv.z * sa[h + 2] + wv.w * sa[h + 3];
    float acc2 = wv.x * sa[HID + h + 0] + wv.y * sa[HID + h + 1]
               + wv.z * sa[HID + h + 2] + wv.w * sa[HID + h + 3];

#pragma unroll
    for (int o = 16; o; o >>= 1) {
        acc1 += __shfl_down_sync(0xffffffffu, acc1, o);
        acc2 += __shfl_down_sync(0xffffffffu, acc2, o);
    }
    if (lane == 0) {
        g_w1[d] = acc1;
        g_w2[d] = acc2;
    }
}

// ---------------------------------------------------------------------------
// Kernel B: s1[r] = context[r,:].w1 ; s2[r] = context[r,:].w2
// 2 rows per warp (4 independent float4 loads in flight), 16 rows per block.
// ---------------------------------------------------------------------------
__global__ void __launch_bounds__(256) proj_kernel(const float* __restrict__ ctx) {
    __shared__ float sw1[IN_DIM];
    __shared__ float sw2[IN_DIM];
    const int t = threadIdx.x;
    sw1[t] = g_w1[t];
    sw2[t] = g_w2[t];
    __syncthreads();

    const int warp = t >> 5;
    const int lane = t & 31;
    const long long r0 = (long long)blockIdx.x * 16 + warp * 2;

    const float4* p0 = (const float4*)(ctx + r0 * IN_DIM);
    const float4* p1 = (const float4*)(ctx + (r0 + 1) * IN_DIM);

    // front-batch 4 independent loads
    const float4 v0a = __ldcs(&p0[lane]);
    const float4 v0b = __ldcs(&p0[lane + 32]);
    const float4 v1a = __ldcs(&p1[lane]);
    const float4 v1b = __ldcs(&p1[lane + 32]);

    const int da = lane * 4;
    const int db = (lane + 32) * 4;

    float a10 = 0.f, a20 = 0.f, a11 = 0.f, a21 = 0.f;
    a10 = fmaf(v0a.x, sw1[da+0], a10); a10 = fmaf(v0a.y, sw1[da+1], a10);
    a10 = fmaf(v0a.z, sw1[da+2], a10); a10 = fmaf(v0a.w, sw1[da+3], a10);
    a10 = fmaf(v0b.x, sw1[db+0], a10); a10 = fmaf(v0b.y, sw1[db+1], a10);
    a10 = fmaf(v0b.z, sw1[db+2], a10); a10 = fmaf(v0b.w, sw1[db+3], a10);

    a20 = fmaf(v0a.x, sw2[da+0], a20); a20 = fmaf(v0a.y, sw2[da+1], a20);
    a20 = fmaf(v0a.z, sw2[da+2], a20); a20 = fmaf(v0a.w, sw2[da+3], a20);
    a20 = fmaf(v0b.x, sw2[db+0], a20); a20 = fmaf(v0b.y, sw2[db+1], a20);
    a20 = fmaf(v0b.z, sw2[db+2], a20); a20 = fmaf(v0b.w, sw2[db+3], a20);

    a11 = fmaf(v1a.x, sw1[da+0], a11); a11 = fmaf(v1a.y, sw1[da+1], a11);
    a11 = fmaf(v1a.z, sw1[da+2], a11); a11 = fmaf(v1a.w, sw1[da+3], a11);
    a11 = fmaf(v1b.x, sw1[db+0], a11); a11 = fmaf(v1b.y, sw1[db+1], a11);
    a11 = fmaf(v1b.z, sw1[db+2], a11); a11 = fmaf(v1b.w, sw1[db+3], a11);

    a21 = fmaf(v1a.x, sw2[da+0], a21); a21 = fmaf(v1a.y, sw2[da+1], a21);
    a21 = fmaf(v1a.z, sw2[da+2], a21); a21 = fmaf(v1a.w, sw2[da+3], a21);
    a21 = fmaf(v1b.x, sw2[db+0], a21); a21 = fmaf(v1b.y, sw2[db+1], a21);
    a21 = fmaf(v1b.z, sw2[db+2], a21); a21 = fmaf(v1b.w, sw2[db+3], a21);

#pragma unroll
    for (int o = 16; o; o >>= 1) {
        a10 += __shfl_down_sync(0xffffffffu, a10, o);
        a20 += __shfl_down_sync(0xffffffffu, a20, o);
        a11 += __shfl_down_sync(0xffffffffu, a11, o);
        a21 += __shfl_down_sync(0xffffffffu, a21, o);
    }
    if (lane == 0) {
        g_s1[r0]     = a10;
        g_s2[r0]     = a20;
        g_s1[r0 + 1] = a11;
        g_s2[r0 + 1] = a21;
    }
}

// ---------------------------------------------------------------------------
// Kernel C: warp-per-row attention. 8 rows per 256-thread block (same batch).
// Each lane: 32 j's via 8 int4 adj loads (front-batched, MLP=8).
// Warp-shfl reductions only (no block syncs after smem fill).
// softplus(x), x in [0,1], via even/odd series -> no exp/log in epilogue.
// ---------------------------------------------------------------------------
__global__ void __launch_bounds__(256) attn_kernel(const int* __restrict__ adj,
                                                   float* __restrict__ out) {
    const int rowbase = blockIdx.x * 8;
    const int b = rowbase >> 10;

    __shared__ float4 s2s[NN / 4];     // 4KB: s2 for this batch

    const int t = threadIdx.x;
    const int warp = t >> 5;
    const int lane = t & 31;

    s2s[t] = ((const float4*)(g_s2 + b * NN))[t];
    __syncthreads();

    const int row = rowbase + warp;
    const float s1v = g_s1[row];

    const int4* ap = (const int4*)(adj + (long long)row * NN);
    int4 a4[8];
#pragma unroll
    for (int k = 0; k < 8; ++k)
        a4[k] = __ldcs(&ap[k * 32 + lane]);

    float ev[32];
#pragma unroll
    for (int k = 0; k < 8; ++k) {
        const float4 s2v = s2s[k * 32 + lane];
        float e;
        e = s1v + s2v.x; e = (e >= 0.f) ? e : NEG_SLOPE * e; ev[4*k+0] = (a4[k].x > 0) ? e : MASK_VAL;
        e = s1v + s2v.y; e = (e >= 0.f) ? e : NEG_SLOPE * e; ev[4*k+1] = (a4[k].y > 0) ? e : MASK_VAL;
        e = s1v + s2v.z; e = (e >= 0.f) ? e : NEG_SLOPE * e; ev[4*k+2] = (a4[k].z > 0) ? e : MASK_VAL;
        e = s1v + s2v.w; e = (e >= 0.f) ? e : NEG_SLOPE * e; ev[4*k+3] = (a4[k].w > 0) ? e : MASK_VAL;
    }

    // warp max
    float m = ev[0];
#pragma unroll
    for (int i = 1; i < 32; ++i) m = fmaxf(m, ev[i]);
#pragma unroll
    for (int o = 16; o; o >>= 1)
        m = fmaxf(m, __shfl_xor_sync(0xffffffffu, m, o));

    // exp + warp sum
    float s = 0.f;
#pragma unroll
    for (int i = 0; i < 32; ++i) {
        ev[i] = __expf(ev[i] - m);     // masked -> 0; all-masked row -> 1 each
        s += ev[i];
    }
#pragma unroll
    for (int o = 16; o; o >>= 1)
        s += __shfl_xor_sync(0xffffffffu, s, o);
    const float inv = __frcp_rn(s);

    // softplus(x) = ln2 + x/2 + x^2*(1/8 + x^2*(-1/192 + x^2/2880)), x in [0,1]
    float4* op = (float4*)(out + (long long)row * NN);
#pragma unroll
    for (int k = 0; k < 8; ++k) {
        float4 o4;
        float r[4];
#pragma unroll
        for (int c = 0; c < 4; ++c) {
            const float x = ev[4*k+c] * inv;
            const float x2 = x * x;
            float pl = fmaf(x2, 3.472222e-4f, -5.2083335e-3f);
            pl = fmaf(x2, pl, 0.125f);
            pl = fmaf(x2, pl, 0.f);
            r[c] = fmaf(0.5f, x, LN2) + pl * x2;
        }
        o4.x = r[0]; o4.y = r[1]; o4.z = r[2]; o4.w = r[3];
        __stcs(&op[k * 32 + lane], o4);
    }
}

extern "C" void kernel_launch(void* const* d_in, const int* in_sizes, int n_in,
                              void* d_out, int out_size) {
    const float* ctx = (const float*)d_in[0];   // (64,1024,256)
    const float* W   = (const float*)d_in[1];   // (256,128)
    const float* a   = (const float*)d_in[2];   // (256,1)
    const int*   adj = (const int*)d_in[3];     // (64,1024,1024)
    float* out = (float*)d_out;

    fold_a_kernel<<<32, 256>>>(W, a);
    proj_kernel<<<(BATCH * NN) / 16, 256>>>(ctx);
    attn_kernel<<<(BATCH * NN) / 8, 256>>>(adj, out);
}

// round 5
// speedup vs baseline: 1.6340x; 1.0087x over previous
#include <cuda_runtime.h>
#include <cuda_bf16.h>

#define BATCH 64
#define NN 1024
#define IN_DIM 256
#define HID 128
#define NEG_SLOPE 0.2f
#define MASK_VAL (-9.0e15f)
#define LN2 0.69314718056f

// scratch (allocation-free rule: __device__ globals)
__device__ float g_w1[IN_DIM];
__device__ float g_w2[IN_DIM];
__device__ float g_s1[BATCH * NN];
__device__ float g_s2[BATCH * NN];

// PDL primitives
__device__ __forceinline__ void gdc_wait() {
    asm volatile("griddepcontrol.wait;" ::: "memory");
}
__device__ __forceinline__ void gdc_launch_dependents() {
    asm volatile("griddepcontrol.launch_dependents;" ::: "memory");
}

// ---------------------------------------------------------------------------
// Kernel A: w1 = W @ a[:HID], w2 = W @ a[HID:]. One warp per output d.
// Triggers dependent launch as soon as stores are issued.
// ---------------------------------------------------------------------------
__global__ void fold_a_kernel(const float* __restrict__ W,
                              const float* __restrict__ a) {
    __shared__ float sa[2 * HID];
    const int t = threadIdx.x;         // 0..255
    sa[t] = a[t];
    __syncthreads();

    const int warp = t >> 5;
    const int lane = t & 31;
    const int d = blockIdx.x * 8 + warp;      // 0..255

    const float4 wv = ((const float4*)(W + d * HID))[lane];
    const int h = lane * 4;
    float acc1 = wv.x * sa[h + 0] + wv.y * sa[h + 1]
               + wv.z * sa[h + 2] + wv.w * sa[h + 3];
    float acc2 = wv.x * sa[HID + h + 0] + wv.y * sa[HID + h + 1]
               + wv.z * sa[HID + h + 2] + wv.w * sa[HID + h + 3];

#pragma unroll
    for (int o = 16; o; o >>= 1) {
        acc1 += __shfl_down_sync(0xffffffffu, acc1, o);
        acc2 += __shfl_down_sync(0xffffffffu, acc2, o);
    }
    if (lane == 0) {
        g_w1[d] = acc1;
        g_w2[d] = acc2;
    }
    __syncthreads();
    gdc_launch_dependents();
}

// ---------------------------------------------------------------------------
// Kernel B: s1[r] = ctx[r,:].w1 ; s2[r] = ctx[r,:].w2
// 4 rows per warp (8 independent float4 loads in flight), 32 rows per block.
// PDL: ctx loads issued BEFORE waiting on fold's w1/w2.
// ---------------------------------------------------------------------------
__global__ void __launch_bounds__(256) proj_kernel(const float* __restrict__ ctx) {
    __shared__ float sw1[IN_DIM];
    __shared__ float sw2[IN_DIM];
    const int t = threadIdx.x;
    const int warp = t >> 5;
    const int lane = t & 31;
    const long long r0 = (long long)blockIdx.x * 32 + warp * 4;

    // front-batch 8 independent loads (covers fold's latency via PDL)
    float4 va[4], vb[4];
#pragma unroll
    for (int r = 0; r < 4; ++r) {
        const float4* p = (const float4*)(ctx + (r0 + r) * IN_DIM);
        va[r] = __ldcs(&p[lane]);
        vb[r] = __ldcs(&p[lane + 32]);
    }

    gdc_wait();                        // fold results now visible
    sw1[t] = g_w1[t];
    sw2[t] = g_w2[t];
    __syncthreads();

    const int da = lane * 4;
    const int db = (lane + 32) * 4;
    float s1v[4], s2v[4];
#pragma unroll
    for (int r = 0; r < 4; ++r) {
        float x1 = 0.f, x2 = 0.f;
        x1 = fmaf(va[r].x, sw1[da+0], x1); x1 = fmaf(va[r].y, sw1[da+1], x1);
        x1 = fmaf(va[r].z, sw1[da+2], x1); x1 = fmaf(va[r].w, sw1[da+3], x1);
        x1 = fmaf(vb[r].x, sw1[db+0], x1); x1 = fmaf(vb[r].y, sw1[db+1], x1);
        x1 = fmaf(vb[r].z, sw1[db+2], x1); x1 = fmaf(vb[r].w, sw1[db+3], x1);
        x2 = fmaf(va[r].x, sw2[da+0], x2); x2 = fmaf(va[r].y, sw2[da+1], x2);
        x2 = fmaf(va[r].z, sw2[da+2], x2); x2 = fmaf(va[r].w, sw2[da+3], x2);
        x2 = fmaf(vb[r].x, sw2[db+0], x2); x2 = fmaf(vb[r].y, sw2[db+1], x2);
        x2 = fmaf(vb[r].z, sw2[db+2], x2); x2 = fmaf(vb[r].w, sw2[db+3], x2);
        s1v[r] = x1;
        s2v[r] = x2;
    }
#pragma unroll
    for (int o = 16; o; o >>= 1) {
#pragma unroll
        for (int r = 0; r < 4; ++r) {
            s1v[r] += __shfl_down_sync(0xffffffffu, s1v[r], o);
            s2v[r] += __shfl_down_sync(0xffffffffu, s2v[r], o);
        }
    }
    if (lane == 0) {
#pragma unroll
        for (int r = 0; r < 4; ++r) {
            g_s1[r0 + r] = s1v[r];
            g_s2[r0 + r] = s2v[r];
        }
    }
    gdc_launch_dependents();
}

// ---------------------------------------------------------------------------
// Kernel C: warp-per-row attention. 8 rows per 256-thread block (same batch).
// PDL: adj loads (bulk of traffic) issued BEFORE waiting on proj's s1/s2.
// ---------------------------------------------------------------------------
__global__ void __launch_bounds__(256) attn_kernel(const int* __restrict__ adj,
                                                   float* __restrict__ out) {
    const int rowbase = blockIdx.x * 8;
    const int b = rowbase >> 10;

    __shared__ float4 s2s[NN / 4];     // 4KB: s2 for this batch

    const int t = threadIdx.x;
    const int warp = t >> 5;
    const int lane = t & 31;
    const int row = rowbase + warp;

    // front-batch adj loads (independent of proj results)
    const int4* ap = (const int4*)(adj + (long long)row * NN);
    int4 a4[8];
#pragma unroll
    for (int k = 0; k < 8; ++k)
        a4[k] = __ldcs(&ap[k * 32 + lane]);

    gdc_wait();                        // proj results now visible
    s2s[t] = ((const float4*)(g_s2 + b * NN))[t];
    const float s1v = g_s1[row];
    __syncthreads();

    float ev[32];
#pragma unroll
    for (int k = 0; k < 8; ++k) {
        const float4 s2v = s2s[k * 32 + lane];
        float e;
        e = s1v + s2v.x; e = (e >= 0.f) ? e : NEG_SLOPE * e; ev[4*k+0] = (a4[k].x > 0) ? e : MASK_VAL;
        e = s1v + s2v.y; e = (e >= 0.f) ? e : NEG_SLOPE * e; ev[4*k+1] = (a4[k].y > 0) ? e : MASK_VAL;
        e = s1v + s2v.z; e = (e >= 0.f) ? e : NEG_SLOPE * e; ev[4*k+2] = (a4[k].z > 0) ? e : MASK_VAL;
        e = s1v + s2v.w; e = (e >= 0.f) ? e : NEG_SLOPE * e; ev[4*k+3] = (a4[k].w > 0) ? e : MASK_VAL;
    }

    // warp max
    float m = ev[0];
#pragma unroll
    for (int i = 1; i < 32; ++i) m = fmaxf(m, ev[i]);
#pragma unroll
    for (int o = 16; o; o >>= 1)
        m = fmaxf(m, __shfl_xor_sync(0xffffffffu, m, o));

    // exp + warp sum
    float s = 0.f;
#pragma unroll
    for (int i = 0; i < 32; ++i) {
        ev[i] = __expf(ev[i] - m);     // masked -> 0; all-masked row -> 1 each
        s += ev[i];
    }
#pragma unroll
    for (int o = 16; o; o >>= 1)
        s += __shfl_xor_sync(0xffffffffu, s, o);
    const float inv = __frcp_rn(s);

    // softplus(x) = ln2 + x/2 + x^2*(1/8 + x^2*(-1/192 + x^2/2880)), x in [0,1]
    float4* op = (float4*)(out + (long long)row * NN);
#pragma unroll
    for (int k = 0; k < 8; ++k) {
        float4 o4;
        float r[4];
#pragma unroll
        for (int c = 0; c < 4; ++c) {
            const float x = ev[4*k+c] * inv;
            const float x2 = x * x;
            float pl = fmaf(x2, 3.472222e-4f, -5.2083335e-3f);
            pl = fmaf(x2, pl, 0.125f);
            r[c] = fmaf(0.5f, x, LN2) + pl * x2;
        }
        o4.x = r[0]; o4.y = r[1]; o4.z = r[2]; o4.w = r[3];
        __stcs(&op[k * 32 + lane], o4);
    }
}

extern "C" void kernel_launch(void* const* d_in, const int* in_sizes, int n_in,
                              void* d_out, int out_size) {
    const float* ctx = (const float*)d_in[0];   // (64,1024,256)
    const float* W   = (const float*)d_in[1];   // (256,128)
    const float* a   = (const float*)d_in[2];   // (256,1)
    const int*   adj = (const int*)d_in[3];     // (64,1024,1024)
    float* out = (float*)d_out;

    // fold: plain launch
    fold_a_kernel<<<32, 256>>>(W, a);

    // proj: PDL — may launch while fold still running
    {
        cudaLaunchConfig_t cfg = {};
        cudaLaunchAttribute attr[1];
        attr[0].id = cudaLaunchAttributeProgrammaticStreamSerialization;
        attr[0].val.programmaticStreamSerializationAllowed = 1;
        cfg.gridDim = dim3((BATCH * NN) / 32, 1, 1);
        cfg.blockDim = dim3(256, 1, 1);
        cfg.attrs = attr;
        cfg.numAttrs = 1;
        cudaLaunchKernelEx(&cfg, proj_kernel, ctx);
    }

    // attn: PDL — may launch while proj still running
    {
        cudaLaunchConfig_t cfg = {};
        cudaLaunchAttribute attr[1];
        attr[0].id = cudaLaunchAttributeProgrammaticStreamSerialization;
        attr[0].val.programmaticStreamSerializationAllowed = 1;
        cfg.gridDim = dim3((BATCH * NN) / 8, 1, 1);
        cfg.blockDim = dim3(256, 1, 1);
        cfg.attrs = attr;
        cfg.numAttrs = 1;
        cudaLaunchKernelEx(&cfg, attn_kernel, adj, out);
    }
}